// round 13
// baseline (speedup 1.0000x reference)
#include <cuda_runtime.h>

#define N_NODES  20000
#define N_EDGES  320000
#define F_EDGE   32
#define D_IN     16
#define D_NN     16
#define D_GAT    64
#define HID      128
#define N_GRAPHS 64
#define NEG_SLOPE 0.2f

// ---------------- scratch (zero-initialized at load; hist self-cleaned by k_scan) ----------------
static __device__ __align__(16) float g_WeT[F_EDGE * D_IN * D_NN];   // WeT[f][o][i]
static __device__ __align__(16) float g_agg[N_NODES * D_NN];
static __device__ __align__(16) float g_hp[N_NODES * D_GAT];
static __device__ __align__(16) float g_pooled[N_GRAPHS * D_GAT];
static __device__ float g_scs[N_NODES];
static __device__ float g_scd[N_NODES];
static __device__ float g_eself[N_NODES];
static __device__ float g_selfw[N_NODES];
static __device__ float g_invden[N_NODES];
static __device__ float g_cnt[N_GRAPHS];
// sorting scratch
static __device__ int g_hist_src[N_NODES], g_hist_dst[N_NODES];
static __device__ int g_rp_src[N_NODES + 1], g_rp_dst[N_NODES + 1];
static __device__ int g_cur_src[N_NODES], g_cur_dst[N_NODES];
static __device__ __align__(8) int2 g_se_ed[N_EDGES];  // by-src order: (edge id, dst)
static __device__ int g_de_s[N_EDGES];                 // by-dst order: src ids
static __device__ float g_ev[N_EDGES];                 // softmax buffer

// ---------------- helpers ----------------
__device__ __forceinline__ void red_add_v4(float* p, float4 v) {
    asm volatile("red.global.add.v4.f32 [%0], {%1,%2,%3,%4};"
                 :: "l"(p), "f"(v.x), "f"(v.y), "f"(v.z), "f"(v.w) : "memory");
}
__device__ __forceinline__ void red_add_f32(float* p, float v) {
    asm volatile("red.global.add.f32 [%0], %1;" :: "l"(p), "f"(v) : "memory");
}
__device__ __forceinline__ float lrelu(float v) { return v > 0.f ? v : NEG_SLOPE * v; }

// ---------------- K0: histograms + WeT transpose + zero accumulators (fused) ----------------
__global__ void k_hist(const int* __restrict__ ei, const float* __restrict__ We) {
    int t = blockIdx.x * blockDim.x + threadIdx.x;
    int stride = gridDim.x * blockDim.x;
    for (int i = t; i < F_EDGE * D_IN * D_NN; i += stride) {
        int f = i >> 8, r = i & 255, o = r >> 4, ii = r & 15;
        g_WeT[(f << 8) + (o << 4) + ii] = We[(f << 8) + (ii << 4) + o];
    }
    for (int i = t; i < N_NODES * D_NN; i += stride) g_agg[i] = 0.f;
    for (int i = t; i < N_GRAPHS * D_GAT; i += stride) g_pooled[i] = 0.f;
    for (int i = t; i < N_GRAPHS; i += stride) g_cnt[i] = 0.f;
    for (int e = t; e < N_EDGES; e += stride) {
        atomicAdd(&g_hist_src[ei[e]], 1);
        atomicAdd(&g_hist_dst[ei[N_EDGES + e]], 1);
    }
}

// ---------------- K1: exclusive scan of both histograms (shfl-based, self-cleans hist) ----------------
#define SCAN_CHUNK 20
__global__ void k_scan() {
    int* hist = (blockIdx.x == 0) ? g_hist_src : g_hist_dst;
    int* rp   = (blockIdx.x == 0) ? g_rp_src   : g_rp_dst;
    int* cur  = (blockIdx.x == 0) ? g_cur_src  : g_cur_dst;
    __shared__ int wsum[32];
    int tid = threadIdx.x;
    int lane = tid & 31, wid = tid >> 5;
    int base = tid * SCAN_CHUNK;
    int local[SCAN_CHUNK];
    int s = 0;
#pragma unroll
    for (int k = 0; k < SCAN_CHUNK; k++) {
        int idx = base + k;
        int v = 0;
        if (idx < N_NODES) { v = hist[idx]; hist[idx] = 0; }   // read + self-clean
        local[k] = s; s += v;
    }
    int sc = s;
#pragma unroll
    for (int off = 1; off < 32; off <<= 1) {
        int tv = __shfl_up_sync(0xffffffffu, sc, off);
        if (lane >= off) sc += tv;
    }
    if (lane == 31) wsum[wid] = sc;
    __syncthreads();
    if (wid == 0) {
        int v = wsum[lane];
#pragma unroll
        for (int off = 1; off < 32; off <<= 1) {
            int tv = __shfl_up_sync(0xffffffffu, v, off);
            if (lane >= off) v += tv;
        }
        wsum[lane] = v;
    }
    __syncthreads();
    int offset = sc - s + (wid > 0 ? wsum[wid - 1] : 0);   // exclusive prefix of this thread
#pragma unroll
    for (int k = 0; k < SCAN_CHUNK; k++) {
        int idx = base + k;
        if (idx < N_NODES) { rp[idx] = offset + local[k]; cur[idx] = offset + local[k]; }
    }
    if (tid == 1023) rp[N_NODES] = offset + s;
}

// ---------------- K2: scatter into both sorted orders (4 edges/thread, int4 loads) ----------------
__global__ void k_scatter(const int* __restrict__ ei) {
    int t = blockIdx.x * blockDim.x + threadIdx.x;
    if (t >= N_EDGES / 4) return;
    int4 s4 = *reinterpret_cast<const int4*>(&ei[4 * t]);
    int4 d4 = *reinterpret_cast<const int4*>(&ei[N_EDGES + 4 * t]);
    int p0 = atomicAdd(&g_cur_src[s4.x], 1);
    int p1 = atomicAdd(&g_cur_src[s4.y], 1);
    int p2 = atomicAdd(&g_cur_src[s4.z], 1);
    int p3 = atomicAdd(&g_cur_src[s4.w], 1);
    int q0 = atomicAdd(&g_cur_dst[d4.x], 1);
    int q1 = atomicAdd(&g_cur_dst[d4.y], 1);
    int q2 = atomicAdd(&g_cur_dst[d4.z], 1);
    int q3 = atomicAdd(&g_cur_dst[d4.w], 1);
    g_se_ed[p0] = make_int2(4 * t + 0, d4.x);
    g_se_ed[p1] = make_int2(4 * t + 1, d4.y);
    g_se_ed[p2] = make_int2(4 * t + 2, d4.z);
    g_se_ed[p3] = make_int2(4 * t + 3, d4.w);
    g_de_s[q0] = s4.x;
    g_de_s[q1] = s4.y;
    g_de_s[q2] = s4.z;
    g_de_s[q3] = s4.w;
}

// ---------------- K3 (profiled slot): NNConv v7 — sequential halves, 16-reg X2, 4 blocks/SM ----------------
#define EA_CHUNK 8
__global__ void __launch_bounds__(256, 4) k_nnconv(const float* __restrict__ x,
                                                   const float* __restrict__ ea) {
    __shared__ __align__(16) float s_ea[8][EA_CHUNK][F_EDGE];   // 8 KB
    int w = (blockIdx.x * blockDim.x + threadIdx.x) >> 5;  // warp id < 10000
    int wl = threadIdx.x >> 5;
    int lane = threadIdx.x & 31;
    int g = lane >> 4, o = lane & 15;

#pragma unroll
    for (int half = 0; half < 2; half++) {
        int n = 2 * w + half;
        // build X2 for this node only (16 regs; registers reused across halves)
        float X2[16];
        {
            float4 xv0 = *reinterpret_cast<const float4*>(&x[n * D_IN + 0]);
            float4 xv1 = *reinterpret_cast<const float4*>(&x[n * D_IN + 4]);
            float4 xv2 = *reinterpret_cast<const float4*>(&x[n * D_IN + 8]);
            float4 xv3 = *reinterpret_cast<const float4*>(&x[n * D_IN + 12]);
#pragma unroll
            for (int k = 0; k < 16; k++) {
                const float4* wt = reinterpret_cast<const float4*>(
                    &g_WeT[((16 * g + k) << 8) + (o << 4)]);
                float4 w0 = wt[0], w1 = wt[1], w2 = wt[2], w3 = wt[3];
                float s0 = w0.x * xv0.x + w0.y * xv0.y + w0.z * xv0.z + w0.w * xv0.w;
                float s1 = w1.x * xv1.x + w1.y * xv1.y + w1.z * xv1.z + w1.w * xv1.w;
                float s2 = w2.x * xv2.x + w2.y * xv2.y + w2.z * xv2.z + w2.w * xv2.w;
                float s3 = w3.x * xv3.x + w3.y * xv3.y + w3.z * xv3.z + w3.w * xv3.w;
                X2[k] = (s0 + s1) + (s2 + s3);
            }
        }

        int beg = g_rp_src[n], end = g_rp_src[n + 1];
        for (int base = beg; base < end; base += EA_CHUNK) {
            int nleft = min(EA_CHUNK, end - base);
            // stage ea rows for up to 8 edges (2 coalesced rounds)
#pragma unroll
            for (int r = 0; r < 2; r++) {
                int item = lane + 32 * r;         // 0..63
                int i = item >> 3, c = item & 7;
                if (i < nleft) {
                    int e = g_se_ed[base + i].x;
                    *reinterpret_cast<float4*>(&s_ea[wl][i][c * 4]) =
                        *reinterpret_cast<const float4*>(&ea[(size_t)e * F_EDGE + c * 4]);
                }
            }
            __syncwarp();
#pragma unroll 2
            for (int i = 0; i < nleft; i++) {
                int d = g_se_ed[base + i].y;   // broadcast, L1-hot
                const float4* ar = reinterpret_cast<const float4*>(&s_ea[wl][i][g * 16]);
                float4 a0 = ar[0], a1 = ar[1], a2 = ar[2], a3 = ar[3];
                float q0 = a0.x * X2[0]  + a0.y * X2[1]  + a0.z * X2[2]  + a0.w * X2[3];
                float q1 = a1.x * X2[4]  + a1.y * X2[5]  + a1.z * X2[6]  + a1.w * X2[7];
                float q2 = a2.x * X2[8]  + a2.y * X2[9]  + a2.z * X2[10] + a2.w * X2[11];
                float q3 = a3.x * X2[12] + a3.y * X2[13] + a3.z * X2[14] + a3.w * X2[15];
                float p = (q0 + q1) + (q2 + q3);
                p += __shfl_xor_sync(0xffffffffu, p, 16);
                if (lane < 16) red_add_f32(&g_agg[d * D_NN + lane], p);
            }
            __syncwarp();
        }
    }
}

// ---------------- K4: cooperative node transform (16 threads/node) ----------------
__global__ void k_node1(const float* __restrict__ x, const float* __restrict__ Wroot,
                        const float* __restrict__ be, const float* __restrict__ bconv,
                        const float* __restrict__ Wgat,
                        const float* __restrict__ a_src, const float* __restrict__ a_dst) {
    int tid = threadIdx.x;
    int n = blockIdx.x * 8 + (tid >> 4);   // exact grid
    int j = tid & 15;
    __shared__ float sh[128];

    float xj = __ldg(&x[n * D_IN + j]);
    float a = g_agg[n * D_NN + j] + __ldg(&bconv[j]);
#pragma unroll
    for (int i = 0; i < D_IN; i++)
        a += __shfl_sync(0xffffffffu, xj, i, 16) *
             (__ldg(&Wroot[i * D_NN + j]) + __ldg(&be[i * D_NN + j]));
    float hj = fmaxf(a, 0.f);
    sh[tid] = hj;
    __syncwarp();
    const float* shh = &sh[tid & ~15];

    float4 hp4 = make_float4(0.f, 0.f, 0.f, 0.f);
#pragma unroll
    for (int i = 0; i < D_NN; i++) {
        float hv = shh[i];
        float4 wg = *reinterpret_cast<const float4*>(&Wgat[i * D_GAT + j * 4]);
        hp4.x += hv * wg.x; hp4.y += hv * wg.y; hp4.z += hv * wg.z; hp4.w += hv * wg.w;
    }
    *reinterpret_cast<float4*>(&g_hp[(size_t)n * D_GAT + j * 4]) = hp4;

    float4 as = *reinterpret_cast<const float4*>(&a_src[j * 4]);
    float4 ad = *reinterpret_cast<const float4*>(&a_dst[j * 4]);
    float ss = hp4.x * as.x + hp4.y * as.y + hp4.z * as.z + hp4.w * as.w;
    float sd = hp4.x * ad.x + hp4.y * ad.y + hp4.z * ad.z + hp4.w * ad.w;
#pragma unroll
    for (int off = 8; off >= 1; off >>= 1) {
        ss += __shfl_xor_sync(0xffffffffu, ss, off, 16);
        sd += __shfl_xor_sync(0xffffffffu, sd, off, 16);
    }
    if (j == 0) {
        g_scs[n] = ss;
        g_scd[n] = sd;
        g_eself[n] = lrelu(ss + sd);
    }
}

// ---------------- K5: GAT softmax per dst node (warp/node, no atomics) ----------------
__global__ void k_softmax() {
    int n = blockIdx.x * 8 + (threadIdx.x >> 5);   // exact grid
    int lane = threadIdx.x & 31;
    int beg = g_rp_dst[n], end = g_rp_dst[n + 1];
    float scd_n = g_scd[n];
    float eself = g_eself[n];

    float m = eself;
    for (int j = beg + lane; j < end; j += 32) {
        float ev = lrelu(g_scs[g_de_s[j]] + scd_n);
        g_ev[j] = ev;
        m = fmaxf(m, ev);
    }
#pragma unroll
    for (int off = 16; off >= 1; off >>= 1)
        m = fmaxf(m, __shfl_xor_sync(0xffffffffu, m, off));

    float sum = 0.f;
    for (int j = beg + lane; j < end; j += 32) {
        float ex = __expf(g_ev[j] - m);
        g_ev[j] = ex;
        sum += ex;
    }
    float exs = __expf(eself - m);
    if (lane == 0) sum += exs;
#pragma unroll
    for (int off = 16; off >= 1; off >>= 1)
        sum += __shfl_xor_sync(0xffffffffu, sum, off);
    if (lane == 0) {
        g_selfw[n] = exs;
        g_invden[n] = 1.f / sum;
    }
}

// ---------------- K6: GAT aggregate + bias/relu + mean-pool scatter (16 threads/node) ----------------
__global__ void k_gatagg(const int* __restrict__ bids, const float* __restrict__ bgat) {
    int tid = threadIdx.x;
    int n = blockIdx.x * 16 + (tid >> 4);   // exact grid
    int og = tid & 15;
    float inv = g_invden[n];
    float w0 = g_selfw[n] * inv;
    float4 acc = *reinterpret_cast<const float4*>(&g_hp[(size_t)n * D_GAT + og * 4]);
    acc.x *= w0; acc.y *= w0; acc.z *= w0; acc.w *= w0;
    int beg = g_rp_dst[n], end = g_rp_dst[n + 1];
    for (int j = beg; j < end; j++) {
        int s = g_de_s[j];
        float w = g_ev[j] * inv;
        float4 v = *reinterpret_cast<const float4*>(&g_hp[(size_t)s * D_GAT + og * 4]);
        acc.x += w * v.x; acc.y += w * v.y; acc.z += w * v.z; acc.w += w * v.w;
    }
    float4 b = *reinterpret_cast<const float4*>(&bgat[og * 4]);
    acc.x = fmaxf(acc.x + b.x, 0.f); acc.y = fmaxf(acc.y + b.y, 0.f);
    acc.z = fmaxf(acc.z + b.z, 0.f); acc.w = fmaxf(acc.w + b.w, 0.f);
    int g = bids[n];
    red_add_v4(&g_pooled[g * D_GAT + og * 4], acc);
    if (og == 0) atomicAdd(&g_cnt[g], 1.f);
}

// ---------------- K7: MLP head, one block per graph ----------------
__global__ void k_head(const float* __restrict__ Wfc1, const float* __restrict__ bfc1,
                       const float* __restrict__ Wfc2, const float* __restrict__ bfc2,
                       float* __restrict__ out) {
    int g = blockIdx.x;
    int h = threadIdx.x;
    __shared__ float sp[D_GAT];
    __shared__ float red[HID];
    if (h < D_GAT) {
        float c = fmaxf(g_cnt[g], 1.f);
        sp[h] = g_pooled[g * D_GAT + h] / c;
    }
    __syncthreads();
    float acc = __ldg(&bfc1[h]);
#pragma unroll 8
    for (int k = 0; k < D_GAT; k++) acc += sp[k] * __ldg(&Wfc1[k * HID + h]);
    acc = fmaxf(acc, 0.f);
    red[h] = acc * __ldg(&Wfc2[h]);
    __syncthreads();
    for (int s = HID / 2; s > 0; s >>= 1) {
        if (h < s) red[h] += red[h + s];
        __syncthreads();
    }
    if (h == 0) out[g] = red[0] + __ldg(&bfc2[0]);
}

// ---------------- launch ----------------
extern "C" void kernel_launch(void* const* d_in, const int* in_sizes, int n_in,
                              void* d_out, int out_size) {
    const float* x     = (const float*)d_in[0];
    const int*   ei    = (const int*)d_in[1];     // int32 (JAX x64 disabled)
    const float* ea    = (const float*)d_in[2];
    const int*   bids  = (const int*)d_in[3];     // int32
    const float* We    = (const float*)d_in[4];
    const float* be    = (const float*)d_in[5];
    const float* Wroot = (const float*)d_in[6];
    const float* bconv = (const float*)d_in[7];
    const float* Wgat  = (const float*)d_in[8];
    const float* a_src = (const float*)d_in[9];
    const float* a_dst = (const float*)d_in[10];
    const float* bgat  = (const float*)d_in[11];
    const float* Wfc1  = (const float*)d_in[12];
    const float* bfc1  = (const float*)d_in[13];
    const float* Wfc2  = (const float*)d_in[14];
    const float* bfc2  = (const float*)d_in[15];
    float* out = (float*)d_out;

    k_hist<<<256, 256>>>(ei, We);                          // idx 0
    k_scan<<<2, 1024>>>();                                 // idx 1
    k_scatter<<<(N_EDGES / 4 + 255) / 256, 256>>>(ei);     // idx 2
    k_nnconv<<<(N_NODES / 2 * 32 + 255) / 256, 256>>>(x, ea);   // idx 3 (profiled)
    k_node1<<<N_NODES / 8, 128>>>(x, Wroot, be, bconv, Wgat, a_src, a_dst);
    k_softmax<<<N_NODES / 8, 256>>>();
    k_gatagg<<<N_NODES / 16, 256>>>(bids, bgat);
    k_head<<<N_GRAPHS, HID>>>(Wfc1, bfc1, Wfc2, bfc2, out);
}

// round 14
// speedup vs baseline: 1.8342x; 1.8342x over previous
#include <cuda_runtime.h>

#define N_NODES  20000
#define N_EDGES  320000
#define F_EDGE   32
#define D_IN     16
#define D_NN     16
#define D_GAT    64
#define HID      128
#define N_GRAPHS 64
#define NEG_SLOPE 0.2f

// ---------------- scratch (zero-initialized at load; hist self-cleaned by k_scan) ----------------
static __device__ __align__(16) float g_WeT[F_EDGE * D_IN * D_NN];   // WeT[f][o][i]
static __device__ __align__(16) float g_agg[N_NODES * D_NN];
static __device__ __align__(16) float g_hp[N_NODES * D_GAT];
static __device__ __align__(16) float g_pooled[N_GRAPHS * D_GAT];
static __device__ float g_scs[N_NODES];
static __device__ float g_scd[N_NODES];
static __device__ float g_eself[N_NODES];
static __device__ float g_selfw[N_NODES];
static __device__ float g_invden[N_NODES];
static __device__ float g_cnt[N_GRAPHS];
// sorting scratch
static __device__ int g_hist_src[N_NODES], g_hist_dst[N_NODES];
static __device__ int g_rp_src[N_NODES + 1], g_rp_dst[N_NODES + 1];
static __device__ int g_cur_src[N_NODES], g_cur_dst[N_NODES];
static __device__ __align__(8) int2 g_se_ed[N_EDGES];  // by-src order: (edge id, dst)
static __device__ int g_de_s[N_EDGES];                 // by-dst order: src ids
static __device__ float g_ev[N_EDGES];                 // softmax buffer

// ---------------- helpers ----------------
__device__ __forceinline__ void red_add_v4(float* p, float4 v) {
    asm volatile("red.global.add.v4.f32 [%0], {%1,%2,%3,%4};"
                 :: "l"(p), "f"(v.x), "f"(v.y), "f"(v.z), "f"(v.w) : "memory");
}
__device__ __forceinline__ void red_add_f32(float* p, float v) {
    asm volatile("red.global.add.f32 [%0], %1;" :: "l"(p), "f"(v) : "memory");
}
__device__ __forceinline__ float lrelu(float v) { return v > 0.f ? v : NEG_SLOPE * v; }

// ---------------- K0: histograms + WeT transpose + zero accumulators (fused) ----------------
__global__ void k_hist(const int* __restrict__ ei, const float* __restrict__ We) {
    int t = blockIdx.x * blockDim.x + threadIdx.x;
    int stride = gridDim.x * blockDim.x;
    for (int i = t; i < F_EDGE * D_IN * D_NN; i += stride) {
        int f = i >> 8, r = i & 255, o = r >> 4, ii = r & 15;
        g_WeT[(f << 8) + (o << 4) + ii] = We[(f << 8) + (ii << 4) + o];
    }
    for (int i = t; i < N_NODES * D_NN; i += stride) g_agg[i] = 0.f;
    for (int i = t; i < N_GRAPHS * D_GAT; i += stride) g_pooled[i] = 0.f;
    for (int i = t; i < N_GRAPHS; i += stride) g_cnt[i] = 0.f;
    for (int e = t; e < N_EDGES; e += stride) {
        atomicAdd(&g_hist_src[ei[e]], 1);
        atomicAdd(&g_hist_dst[ei[N_EDGES + e]], 1);
    }
}

// ---------------- K1: exclusive scan of both histograms (shfl-based, self-cleans hist) ----------------
#define SCAN_CHUNK 20
__global__ void k_scan() {
    int* hist = (blockIdx.x == 0) ? g_hist_src : g_hist_dst;
    int* rp   = (blockIdx.x == 0) ? g_rp_src   : g_rp_dst;
    int* cur  = (blockIdx.x == 0) ? g_cur_src  : g_cur_dst;
    __shared__ int wsum[32];
    int tid = threadIdx.x;
    int lane = tid & 31, wid = tid >> 5;
    int base = tid * SCAN_CHUNK;
    int local[SCAN_CHUNK];
    int s = 0;
#pragma unroll
    for (int k = 0; k < SCAN_CHUNK; k++) {
        int idx = base + k;
        int v = 0;
        if (idx < N_NODES) { v = hist[idx]; hist[idx] = 0; }   // read + self-clean
        local[k] = s; s += v;
    }
    int sc = s;
#pragma unroll
    for (int off = 1; off < 32; off <<= 1) {
        int tv = __shfl_up_sync(0xffffffffu, sc, off);
        if (lane >= off) sc += tv;
    }
    if (lane == 31) wsum[wid] = sc;
    __syncthreads();
    if (wid == 0) {
        int v = wsum[lane];
#pragma unroll
        for (int off = 1; off < 32; off <<= 1) {
            int tv = __shfl_up_sync(0xffffffffu, v, off);
            if (lane >= off) v += tv;
        }
        wsum[lane] = v;
    }
    __syncthreads();
    int offset = sc - s + (wid > 0 ? wsum[wid - 1] : 0);   // exclusive prefix of this thread
#pragma unroll
    for (int k = 0; k < SCAN_CHUNK; k++) {
        int idx = base + k;
        if (idx < N_NODES) { rp[idx] = offset + local[k]; cur[idx] = offset + local[k]; }
    }
    if (tid == 1023) rp[N_NODES] = offset + s;
}

// ---------------- K2: scatter into both sorted orders (4 edges/thread, int4 loads) ----------------
__global__ void k_scatter(const int* __restrict__ ei) {
    int t = blockIdx.x * blockDim.x + threadIdx.x;
    if (t >= N_EDGES / 4) return;
    int4 s4 = *reinterpret_cast<const int4*>(&ei[4 * t]);
    int4 d4 = *reinterpret_cast<const int4*>(&ei[N_EDGES + 4 * t]);
    int p0 = atomicAdd(&g_cur_src[s4.x], 1);
    int p1 = atomicAdd(&g_cur_src[s4.y], 1);
    int p2 = atomicAdd(&g_cur_src[s4.z], 1);
    int p3 = atomicAdd(&g_cur_src[s4.w], 1);
    int q0 = atomicAdd(&g_cur_dst[d4.x], 1);
    int q1 = atomicAdd(&g_cur_dst[d4.y], 1);
    int q2 = atomicAdd(&g_cur_dst[d4.z], 1);
    int q3 = atomicAdd(&g_cur_dst[d4.w], 1);
    g_se_ed[p0] = make_int2(4 * t + 0, d4.x);
    g_se_ed[p1] = make_int2(4 * t + 1, d4.y);
    g_se_ed[p2] = make_int2(4 * t + 2, d4.z);
    g_se_ed[p3] = make_int2(4 * t + 3, d4.w);
    g_de_s[q0] = s4.x;
    g_de_s[q1] = s4.y;
    g_de_s[q2] = s4.z;
    g_de_s[q3] = s4.w;
}

// ---------------- K3 (profiled slot): NNConv v8 — ONE node per warp, 16-reg X2, 4 blocks/SM ----------------
// Single X2 array, no half-loop for ptxas to pipeline -> peak live regs ~55, no spill at 64 cap.
#define EA_CHUNK 8
__global__ void __launch_bounds__(256, 4) k_nnconv(const float* __restrict__ x,
                                                   const float* __restrict__ ea) {
    __shared__ __align__(16) float s_ea[8][EA_CHUNK][F_EDGE];   // 8 KB
    int n = (blockIdx.x * blockDim.x + threadIdx.x) >> 5;  // node id < 20000
    int wl = threadIdx.x >> 5;
    int lane = threadIdx.x & 31;
    int g = lane >> 4, o = lane & 15;

    // build X2 for this node (16 regs)
    float X2[16];
    {
        float4 xv0 = *reinterpret_cast<const float4*>(&x[n * D_IN + 0]);
        float4 xv1 = *reinterpret_cast<const float4*>(&x[n * D_IN + 4]);
        float4 xv2 = *reinterpret_cast<const float4*>(&x[n * D_IN + 8]);
        float4 xv3 = *reinterpret_cast<const float4*>(&x[n * D_IN + 12]);
#pragma unroll
        for (int k = 0; k < 16; k++) {
            const float4* wt = reinterpret_cast<const float4*>(
                &g_WeT[((16 * g + k) << 8) + (o << 4)]);
            float4 w0 = wt[0], w1 = wt[1], w2 = wt[2], w3 = wt[3];
            float s0 = w0.x * xv0.x + w0.y * xv0.y + w0.z * xv0.z + w0.w * xv0.w;
            float s1 = w1.x * xv1.x + w1.y * xv1.y + w1.z * xv1.z + w1.w * xv1.w;
            float s2 = w2.x * xv2.x + w2.y * xv2.y + w2.z * xv2.z + w2.w * xv2.w;
            float s3 = w3.x * xv3.x + w3.y * xv3.y + w3.z * xv3.z + w3.w * xv3.w;
            X2[k] = (s0 + s1) + (s2 + s3);
        }
    }

    int beg = g_rp_src[n], end = g_rp_src[n + 1];
    for (int base = beg; base < end; base += EA_CHUNK) {
        int nleft = min(EA_CHUNK, end - base);
        // stage ea rows for up to 8 edges (2 coalesced rounds)
#pragma unroll
        for (int r = 0; r < 2; r++) {
            int item = lane + 32 * r;         // 0..63
            int i = item >> 3, c = item & 7;
            if (i < nleft) {
                int e = g_se_ed[base + i].x;
                *reinterpret_cast<float4*>(&s_ea[wl][i][c * 4]) =
                    *reinterpret_cast<const float4*>(&ea[(size_t)e * F_EDGE + c * 4]);
            }
        }
        __syncwarp();
#pragma unroll 2
        for (int i = 0; i < nleft; i++) {
            int d = g_se_ed[base + i].y;   // broadcast, L1-hot
            const float4* ar = reinterpret_cast<const float4*>(&s_ea[wl][i][g * 16]);
            float4 a0 = ar[0], a1 = ar[1], a2 = ar[2], a3 = ar[3];
            float q0 = a0.x * X2[0]  + a0.y * X2[1]  + a0.z * X2[2]  + a0.w * X2[3];
            float q1 = a1.x * X2[4]  + a1.y * X2[5]  + a1.z * X2[6]  + a1.w * X2[7];
            float q2 = a2.x * X2[8]  + a2.y * X2[9]  + a2.z * X2[10] + a2.w * X2[11];
            float q3 = a3.x * X2[12] + a3.y * X2[13] + a3.z * X2[14] + a3.w * X2[15];
            float p = (q0 + q1) + (q2 + q3);
            p += __shfl_xor_sync(0xffffffffu, p, 16);
            if (lane < 16) red_add_f32(&g_agg[d * D_NN + lane], p);
        }
        __syncwarp();
    }
}

// ---------------- K4: cooperative node transform (16 threads/node) ----------------
__global__ void k_node1(const float* __restrict__ x, const float* __restrict__ Wroot,
                        const float* __restrict__ be, const float* __restrict__ bconv,
                        const float* __restrict__ Wgat,
                        const float* __restrict__ a_src, const float* __restrict__ a_dst) {
    int tid = threadIdx.x;
    int n = blockIdx.x * 8 + (tid >> 4);   // exact grid
    int j = tid & 15;
    __shared__ float sh[128];

    float xj = __ldg(&x[n * D_IN + j]);
    float a = g_agg[n * D_NN + j] + __ldg(&bconv[j]);
#pragma unroll
    for (int i = 0; i < D_IN; i++)
        a += __shfl_sync(0xffffffffu, xj, i, 16) *
             (__ldg(&Wroot[i * D_NN + j]) + __ldg(&be[i * D_NN + j]));
    float hj = fmaxf(a, 0.f);
    sh[tid] = hj;
    __syncwarp();
    const float* shh = &sh[tid & ~15];

    float4 hp4 = make_float4(0.f, 0.f, 0.f, 0.f);
#pragma unroll
    for (int i = 0; i < D_NN; i++) {
        float hv = shh[i];
        float4 wg = *reinterpret_cast<const float4*>(&Wgat[i * D_GAT + j * 4]);
        hp4.x += hv * wg.x; hp4.y += hv * wg.y; hp4.z += hv * wg.z; hp4.w += hv * wg.w;
    }
    *reinterpret_cast<float4*>(&g_hp[(size_t)n * D_GAT + j * 4]) = hp4;

    float4 as = *reinterpret_cast<const float4*>(&a_src[j * 4]);
    float4 ad = *reinterpret_cast<const float4*>(&a_dst[j * 4]);
    float ss = hp4.x * as.x + hp4.y * as.y + hp4.z * as.z + hp4.w * as.w;
    float sd = hp4.x * ad.x + hp4.y * ad.y + hp4.z * ad.z + hp4.w * ad.w;
#pragma unroll
    for (int off = 8; off >= 1; off >>= 1) {
        ss += __shfl_xor_sync(0xffffffffu, ss, off, 16);
        sd += __shfl_xor_sync(0xffffffffu, sd, off, 16);
    }
    if (j == 0) {
        g_scs[n] = ss;
        g_scd[n] = sd;
        g_eself[n] = lrelu(ss + sd);
    }
}

// ---------------- K5: GAT softmax per dst node (warp/node, no atomics) ----------------
__global__ void k_softmax() {
    int n = blockIdx.x * 8 + (threadIdx.x >> 5);   // exact grid
    int lane = threadIdx.x & 31;
    int beg = g_rp_dst[n], end = g_rp_dst[n + 1];
    float scd_n = g_scd[n];
    float eself = g_eself[n];

    float m = eself;
    for (int j = beg + lane; j < end; j += 32) {
        float ev = lrelu(g_scs[g_de_s[j]] + scd_n);
        g_ev[j] = ev;
        m = fmaxf(m, ev);
    }
#pragma unroll
    for (int off = 16; off >= 1; off >>= 1)
        m = fmaxf(m, __shfl_xor_sync(0xffffffffu, m, off));

    float sum = 0.f;
    for (int j = beg + lane; j < end; j += 32) {
        float ex = __expf(g_ev[j] - m);
        g_ev[j] = ex;
        sum += ex;
    }
    float exs = __expf(eself - m);
    if (lane == 0) sum += exs;
#pragma unroll
    for (int off = 16; off >= 1; off >>= 1)
        sum += __shfl_xor_sync(0xffffffffu, sum, off);
    if (lane == 0) {
        g_selfw[n] = exs;
        g_invden[n] = 1.f / sum;
    }
}

// ---------------- K6: GAT aggregate + bias/relu + mean-pool scatter (16 threads/node) ----------------
__global__ void k_gatagg(const int* __restrict__ bids, const float* __restrict__ bgat) {
    int tid = threadIdx.x;
    int n = blockIdx.x * 16 + (tid >> 4);   // exact grid
    int og = tid & 15;
    float inv = g_invden[n];
    float w0 = g_selfw[n] * inv;
    float4 acc = *reinterpret_cast<const float4*>(&g_hp[(size_t)n * D_GAT + og * 4]);
    acc.x *= w0; acc.y *= w0; acc.z *= w0; acc.w *= w0;
    int beg = g_rp_dst[n], end = g_rp_dst[n + 1];
    for (int j = beg; j < end; j++) {
        int s = g_de_s[j];
        float w = g_ev[j] * inv;
        float4 v = *reinterpret_cast<const float4*>(&g_hp[(size_t)s * D_GAT + og * 4]);
        acc.x += w * v.x; acc.y += w * v.y; acc.z += w * v.z; acc.w += w * v.w;
    }
    float4 b = *reinterpret_cast<const float4*>(&bgat[og * 4]);
    acc.x = fmaxf(acc.x + b.x, 0.f); acc.y = fmaxf(acc.y + b.y, 0.f);
    acc.z = fmaxf(acc.z + b.z, 0.f); acc.w = fmaxf(acc.w + b.w, 0.f);
    int g = bids[n];
    red_add_v4(&g_pooled[g * D_GAT + og * 4], acc);
    if (og == 0) atomicAdd(&g_cnt[g], 1.f);
}

// ---------------- K7: MLP head, one block per graph ----------------
__global__ void k_head(const float* __restrict__ Wfc1, const float* __restrict__ bfc1,
                       const float* __restrict__ Wfc2, const float* __restrict__ bfc2,
                       float* __restrict__ out) {
    int g = blockIdx.x;
    int h = threadIdx.x;
    __shared__ float sp[D_GAT];
    __shared__ float red[HID];
    if (h < D_GAT) {
        float c = fmaxf(g_cnt[g], 1.f);
        sp[h] = g_pooled[g * D_GAT + h] / c;
    }
    __syncthreads();
    float acc = __ldg(&bfc1[h]);
#pragma unroll 8
    for (int k = 0; k < D_GAT; k++) acc += sp[k] * __ldg(&Wfc1[k * HID + h]);
    acc = fmaxf(acc, 0.f);
    red[h] = acc * __ldg(&Wfc2[h]);
    __syncthreads();
    for (int s = HID / 2; s > 0; s >>= 1) {
        if (h < s) red[h] += red[h + s];
        __syncthreads();
    }
    if (h == 0) out[g] = red[0] + __ldg(&bfc2[0]);
}

// ---------------- launch ----------------
extern "C" void kernel_launch(void* const* d_in, const int* in_sizes, int n_in,
                              void* d_out, int out_size) {
    const float* x     = (const float*)d_in[0];
    const int*   ei    = (const int*)d_in[1];     // int32 (JAX x64 disabled)
    const float* ea    = (const float*)d_in[2];
    const int*   bids  = (const int*)d_in[3];     // int32
    const float* We    = (const float*)d_in[4];
    const float* be    = (const float*)d_in[5];
    const float* Wroot = (const float*)d_in[6];
    const float* bconv = (const float*)d_in[7];
    const float* Wgat  = (const float*)d_in[8];
    const float* a_src = (const float*)d_in[9];
    const float* a_dst = (const float*)d_in[10];
    const float* bgat  = (const float*)d_in[11];
    const float* Wfc1  = (const float*)d_in[12];
    const float* bfc1  = (const float*)d_in[13];
    const float* Wfc2  = (const float*)d_in[14];
    const float* bfc2  = (const float*)d_in[15];
    float* out = (float*)d_out;

    k_hist<<<256, 256>>>(ei, We);                          // idx 0
    k_scan<<<2, 1024>>>();                                 // idx 1
    k_scatter<<<(N_EDGES / 4 + 255) / 256, 256>>>(ei);     // idx 2
    k_nnconv<<<(N_NODES * 32) / 256, 256>>>(x, ea);        // idx 3 (profiled)
    k_node1<<<N_NODES / 8, 128>>>(x, Wroot, be, bconv, Wgat, a_src, a_dst);
    k_softmax<<<N_NODES / 8, 256>>>();
    k_gatagg<<<N_NODES / 16, 256>>>(bids, bgat);
    k_head<<<N_GRAPHS, HID>>>(Wfc1, bfc1, Wfc2, bfc2, out);
}

// round 15
// speedup vs baseline: 2.4900x; 1.3575x over previous
#include <cuda_runtime.h>

#define N_NODES  20000
#define N_EDGES  320000
#define F_EDGE   32
#define D_IN     16
#define D_NN     16
#define D_GAT    64
#define HID      128
#define N_GRAPHS 64
#define NEG_SLOPE 0.2f

// ---------------- scratch (zero-initialized at load; hist self-cleaned by k_scan) ----------------
static __device__ __align__(16) float g_WeT[F_EDGE * D_IN * D_NN];   // WeT[f][o][i] == row p=f*16+o
static __device__ __align__(16) float g_agg[N_NODES * D_NN];
static __device__ __align__(16) float g_hp[N_NODES * D_GAT];
static __device__ __align__(16) float g_pooled[N_GRAPHS * D_GAT];
static __device__ float g_scs[N_NODES];
static __device__ float g_scd[N_NODES];
static __device__ float g_eself[N_NODES];
static __device__ float g_selfw[N_NODES];
static __device__ float g_invden[N_NODES];
static __device__ float g_cnt[N_GRAPHS];
// sorting scratch
static __device__ int g_hist_src[N_NODES], g_hist_dst[N_NODES];
static __device__ int g_rp_src[N_NODES + 1], g_rp_dst[N_NODES + 1];
static __device__ int g_cur_src[N_NODES], g_cur_dst[N_NODES];
static __device__ __align__(8) int2 g_se_ed[N_EDGES];  // by-src order: (edge id, dst)
static __device__ int g_de_s[N_EDGES];                 // by-dst order: src ids
static __device__ float g_ev[N_EDGES];                 // softmax buffer

// ---------------- helpers ----------------
__device__ __forceinline__ void red_add_v4(float* p, float4 v) {
    asm volatile("red.global.add.v4.f32 [%0], {%1,%2,%3,%4};"
                 :: "l"(p), "f"(v.x), "f"(v.y), "f"(v.z), "f"(v.w) : "memory");
}
__device__ __forceinline__ void red_add_f32(float* p, float v) {
    asm volatile("red.global.add.f32 [%0], %1;" :: "l"(p), "f"(v) : "memory");
}
__device__ __forceinline__ float lrelu(float v) { return v > 0.f ? v : NEG_SLOPE * v; }

// ---------------- K0: histograms + WeT transpose + zero accumulators (fused) ----------------
__global__ void k_hist(const int* __restrict__ ei, const float* __restrict__ We) {
    int t = blockIdx.x * blockDim.x + threadIdx.x;
    int stride = gridDim.x * blockDim.x;
    for (int i = t; i < F_EDGE * D_IN * D_NN; i += stride) {
        int f = i >> 8, r = i & 255, o = r >> 4, ii = r & 15;
        g_WeT[(f << 8) + (o << 4) + ii] = We[(f << 8) + (ii << 4) + o];
    }
    for (int i = t; i < N_NODES * D_NN; i += stride) g_agg[i] = 0.f;
    for (int i = t; i < N_GRAPHS * D_GAT; i += stride) g_pooled[i] = 0.f;
    for (int i = t; i < N_GRAPHS; i += stride) g_cnt[i] = 0.f;
    for (int e = t; e < N_EDGES; e += stride) {
        atomicAdd(&g_hist_src[ei[e]], 1);
        atomicAdd(&g_hist_dst[ei[N_EDGES + e]], 1);
    }
}

// ---------------- K1: exclusive scan of both histograms (shfl-based, self-cleans hist) ----------------
#define SCAN_CHUNK 20
__global__ void k_scan() {
    int* hist = (blockIdx.x == 0) ? g_hist_src : g_hist_dst;
    int* rp   = (blockIdx.x == 0) ? g_rp_src   : g_rp_dst;
    int* cur  = (blockIdx.x == 0) ? g_cur_src  : g_cur_dst;
    __shared__ int wsum[32];
    int tid = threadIdx.x;
    int lane = tid & 31, wid = tid >> 5;
    int base = tid * SCAN_CHUNK;
    int local[SCAN_CHUNK];
    int s = 0;
#pragma unroll
    for (int k = 0; k < SCAN_CHUNK; k++) {
        int idx = base + k;
        int v = 0;
        if (idx < N_NODES) { v = hist[idx]; hist[idx] = 0; }   // read + self-clean
        local[k] = s; s += v;
    }
    int sc = s;
#pragma unroll
    for (int off = 1; off < 32; off <<= 1) {
        int tv = __shfl_up_sync(0xffffffffu, sc, off);
        if (lane >= off) sc += tv;
    }
    if (lane == 31) wsum[wid] = sc;
    __syncthreads();
    if (wid == 0) {
        int v = wsum[lane];
#pragma unroll
        for (int off = 1; off < 32; off <<= 1) {
            int tv = __shfl_up_sync(0xffffffffu, v, off);
            if (lane >= off) v += tv;
        }
        wsum[lane] = v;
    }
    __syncthreads();
    int offset = sc - s + (wid > 0 ? wsum[wid - 1] : 0);   // exclusive prefix of this thread
#pragma unroll
    for (int k = 0; k < SCAN_CHUNK; k++) {
        int idx = base + k;
        if (idx < N_NODES) { rp[idx] = offset + local[k]; cur[idx] = offset + local[k]; }
    }
    if (tid == 1023) rp[N_NODES] = offset + s;
}

// ---------------- K2: scatter into both sorted orders (2 edges/thread for ILP) ----------------
__global__ void k_scatter(const int* __restrict__ ei) {
    int t = blockIdx.x * blockDim.x + threadIdx.x;
    int e0 = 2 * t, e1 = 2 * t + 1;
    if (e0 >= N_EDGES) return;
    int s0 = ei[e0], d0 = ei[N_EDGES + e0];
    int s1 = 0, d1 = 0;
    bool has1 = (e1 < N_EDGES);
    if (has1) { s1 = ei[e1]; d1 = ei[N_EDGES + e1]; }
    int p0 = atomicAdd(&g_cur_src[s0], 1);
    int q0 = atomicAdd(&g_cur_dst[d0], 1);
    int p1 = 0, q1 = 0;
    if (has1) {
        p1 = atomicAdd(&g_cur_src[s1], 1);
        q1 = atomicAdd(&g_cur_dst[d1], 1);
    }
    g_se_ed[p0] = make_int2(e0, d0);
    g_de_s[q0] = s0;
    if (has1) {
        g_se_ed[p1] = make_int2(e1, d1);
        g_de_s[q1] = s1;
    }
}

// ---------------- K3 (profiled slot): NNConv v9 — block-cooperative X2 build (16 nodes/block) ----------------
// Phase 1: thread t holds WeT rows p={t, t+256} in regs (read ONCE per block = 2KB/node L1)
//          and contracts them against all 16 staged x rows -> s_X2[n][p].
// Phase 2: warp wl loads its 2 nodes' X2 into the proven register layout and runs the R11 edge loop.
#define EA_CHUNK 8
__global__ void __launch_bounds__(256, 3) k_nnconv(const float* __restrict__ x,
                                                   const float* __restrict__ ea) {
    __shared__ __align__(16) float s_X2[16][512];               // 32 KB  [node][f*16+o]
    __shared__ __align__(16) float s_x[16][16];                 // 1 KB
    __shared__ __align__(16) float s_ea[8][EA_CHUNK][F_EDGE];   // 8 KB
    int tid = threadIdx.x;
    int nb0 = blockIdx.x * 16;

    // phase 0: stage x rows (fully coalesced)
    s_x[tid >> 4][tid & 15] = x[(nb0 + (tid >> 4)) * D_IN + (tid & 15)];
    __syncthreads();

    // phase 1: build X2 for all 16 nodes
    {
        int p0 = tid, p1 = tid + 256;
        const float4* wa = reinterpret_cast<const float4*>(&g_WeT[p0 << 4]);
        const float4* wb = reinterpret_cast<const float4*>(&g_WeT[p1 << 4]);
        float4 wa0 = wa[0], wa1 = wa[1], wa2 = wa[2], wa3 = wa[3];
        float4 wb0 = wb[0], wb1 = wb[1], wb2 = wb[2], wb3 = wb[3];
#pragma unroll
        for (int n = 0; n < 16; n++) {
            const float4* xv = reinterpret_cast<const float4*>(&s_x[n][0]);
            float4 x0 = xv[0], x1 = xv[1], x2 = xv[2], x3 = xv[3];
            float a0 = wa0.x * x0.x + wa0.y * x0.y + wa0.z * x0.z + wa0.w * x0.w;
            float a1 = wa1.x * x1.x + wa1.y * x1.y + wa1.z * x1.z + wa1.w * x1.w;
            float a2 = wa2.x * x2.x + wa2.y * x2.y + wa2.z * x2.z + wa2.w * x2.w;
            float a3 = wa3.x * x3.x + wa3.y * x3.y + wa3.z * x3.z + wa3.w * x3.w;
            float b0 = wb0.x * x0.x + wb0.y * x0.y + wb0.z * x0.z + wb0.w * x0.w;
            float b1 = wb1.x * x1.x + wb1.y * x1.y + wb1.z * x1.z + wb1.w * x1.w;
            float b2 = wb2.x * x2.x + wb2.y * x2.y + wb2.z * x2.z + wb2.w * x2.w;
            float b3 = wb3.x * x3.x + wb3.y * x3.y + wb3.z * x3.z + wb3.w * x3.w;
            s_X2[n][p0] = (a0 + a1) + (a2 + a3);
            s_X2[n][p1] = (b0 + b1) + (b2 + b3);
        }
    }
    __syncthreads();

    // phase 2: per-warp edge loops (warp wl -> local nodes 2wl, 2wl+1)
    int wl = tid >> 5;
    int lane = tid & 31;
    int g = lane >> 4, o = lane & 15;
    int n0l = 2 * wl, n1l = 2 * wl + 1;

    float X2a[16], X2b[16];
#pragma unroll
    for (int k = 0; k < 16; k++) {
        X2a[k] = s_X2[n0l][((16 * g + k) << 4) + o];
        X2b[k] = s_X2[n1l][((16 * g + k) << 4) + o];
    }

#pragma unroll
    for (int half = 0; half < 2; half++) {
        int n = nb0 + (half ? n1l : n0l);
        int beg = g_rp_src[n], end = g_rp_src[n + 1];
        for (int base = beg; base < end; base += EA_CHUNK) {
            int nleft = min(EA_CHUNK, end - base);
            // stage ea rows for up to 8 edges (2 coalesced rounds)
#pragma unroll
            for (int r = 0; r < 2; r++) {
                int item = lane + 32 * r;         // 0..63
                int i = item >> 3, c = item & 7;
                if (i < nleft) {
                    int e = g_se_ed[base + i].x;
                    *reinterpret_cast<float4*>(&s_ea[wl][i][c * 4]) =
                        *reinterpret_cast<const float4*>(&ea[(size_t)e * F_EDGE + c * 4]);
                }
            }
            __syncwarp();
#pragma unroll 2
            for (int i = 0; i < nleft; i++) {
                int d = g_se_ed[base + i].y;   // broadcast, L1-hot
                const float4* ar = reinterpret_cast<const float4*>(&s_ea[wl][i][g * 16]);
                float4 a0 = ar[0], a1 = ar[1], a2 = ar[2], a3 = ar[3];
                float q0, q1, q2, q3;
                if (half == 0) {
                    q0 = a0.x * X2a[0]  + a0.y * X2a[1]  + a0.z * X2a[2]  + a0.w * X2a[3];
                    q1 = a1.x * X2a[4]  + a1.y * X2a[5]  + a1.z * X2a[6]  + a1.w * X2a[7];
                    q2 = a2.x * X2a[8]  + a2.y * X2a[9]  + a2.z * X2a[10] + a2.w * X2a[11];
                    q3 = a3.x * X2a[12] + a3.y * X2a[13] + a3.z * X2a[14] + a3.w * X2a[15];
                } else {
                    q0 = a0.x * X2b[0]  + a0.y * X2b[1]  + a0.z * X2b[2]  + a0.w * X2b[3];
                    q1 = a1.x * X2b[4]  + a1.y * X2b[5]  + a1.z * X2b[6]  + a1.w * X2b[7];
                    q2 = a2.x * X2b[8]  + a2.y * X2b[9]  + a2.z * X2b[10] + a2.w * X2b[11];
                    q3 = a3.x * X2b[12] + a3.y * X2b[13] + a3.z * X2b[14] + a3.w * X2b[15];
                }
                float p = (q0 + q1) + (q2 + q3);
                p += __shfl_xor_sync(0xffffffffu, p, 16);
                if (lane < 16) red_add_f32(&g_agg[d * D_NN + lane], p);
            }
            __syncwarp();
        }
    }
}

// ---------------- K4: cooperative node transform (16 threads/node) ----------------
__global__ void k_node1(const float* __restrict__ x, const float* __restrict__ Wroot,
                        const float* __restrict__ be, const float* __restrict__ bconv,
                        const float* __restrict__ Wgat,
                        const float* __restrict__ a_src, const float* __restrict__ a_dst) {
    int tid = threadIdx.x;
    int n = blockIdx.x * 8 + (tid >> 4);   // exact grid
    int j = tid & 15;
    __shared__ float sh[128];

    float xj = __ldg(&x[n * D_IN + j]);
    float a = g_agg[n * D_NN + j] + __ldg(&bconv[j]);
#pragma unroll
    for (int i = 0; i < D_IN; i++)
        a += __shfl_sync(0xffffffffu, xj, i, 16) *
             (__ldg(&Wroot[i * D_NN + j]) + __ldg(&be[i * D_NN + j]));
    float hj = fmaxf(a, 0.f);
    sh[tid] = hj;
    __syncwarp();
    const float* shh = &sh[tid & ~15];

    float4 hp4 = make_float4(0.f, 0.f, 0.f, 0.f);
#pragma unroll
    for (int i = 0; i < D_NN; i++) {
        float hv = shh[i];
        float4 wg = *reinterpret_cast<const float4*>(&Wgat[i * D_GAT + j * 4]);
        hp4.x += hv * wg.x; hp4.y += hv * wg.y; hp4.z += hv * wg.z; hp4.w += hv * wg.w;
    }
    *reinterpret_cast<float4*>(&g_hp[(size_t)n * D_GAT + j * 4]) = hp4;

    float4 as = *reinterpret_cast<const float4*>(&a_src[j * 4]);
    float4 ad = *reinterpret_cast<const float4*>(&a_dst[j * 4]);
    float ss = hp4.x * as.x + hp4.y * as.y + hp4.z * as.z + hp4.w * as.w;
    float sd = hp4.x * ad.x + hp4.y * ad.y + hp4.z * ad.z + hp4.w * ad.w;
#pragma unroll
    for (int off = 8; off >= 1; off >>= 1) {
        ss += __shfl_xor_sync(0xffffffffu, ss, off, 16);
        sd += __shfl_xor_sync(0xffffffffu, sd, off, 16);
    }
    if (j == 0) {
        g_scs[n] = ss;
        g_scd[n] = sd;
        g_eself[n] = lrelu(ss + sd);
    }
}

// ---------------- K5: GAT softmax per dst node (warp/node, no atomics) ----------------
__global__ void k_softmax() {
    int n = blockIdx.x * 8 + (threadIdx.x >> 5);   // exact grid
    int lane = threadIdx.x & 31;
    int beg = g_rp_dst[n], end = g_rp_dst[n + 1];
    float scd_n = g_scd[n];
    float eself = g_eself[n];

    float m = eself;
    for (int j = beg + lane; j < end; j += 32) {
        float ev = lrelu(g_scs[g_de_s[j]] + scd_n);
        g_ev[j] = ev;
        m = fmaxf(m, ev);
    }
#pragma unroll
    for (int off = 16; off >= 1; off >>= 1)
        m = fmaxf(m, __shfl_xor_sync(0xffffffffu, m, off));

    float sum = 0.f;
    for (int j = beg + lane; j < end; j += 32) {
        float ex = __expf(g_ev[j] - m);
        g_ev[j] = ex;
        sum += ex;
    }
    float exs = __expf(eself - m);
    if (lane == 0) sum += exs;
#pragma unroll
    for (int off = 16; off >= 1; off >>= 1)
        sum += __shfl_xor_sync(0xffffffffu, sum, off);
    if (lane == 0) {
        g_selfw[n] = exs;
        g_invden[n] = 1.f / sum;
    }
}

// ---------------- K6: GAT aggregate + bias/relu + mean-pool scatter (16 threads/node) ----------------
__global__ void k_gatagg(const int* __restrict__ bids, const float* __restrict__ bgat) {
    int tid = threadIdx.x;
    int n = blockIdx.x * 16 + (tid >> 4);   // exact grid
    int og = tid & 15;
    float inv = g_invden[n];
    float w0 = g_selfw[n] * inv;
    float4 acc = *reinterpret_cast<const float4*>(&g_hp[(size_t)n * D_GAT + og * 4]);
    acc.x *= w0; acc.y *= w0; acc.z *= w0; acc.w *= w0;
    int beg = g_rp_dst[n], end = g_rp_dst[n + 1];
    for (int j = beg; j < end; j++) {
        int s = g_de_s[j];
        float w = g_ev[j] * inv;
        float4 v = *reinterpret_cast<const float4*>(&g_hp[(size_t)s * D_GAT + og * 4]);
        acc.x += w * v.x; acc.y += w * v.y; acc.z += w * v.z; acc.w += w * v.w;
    }
    float4 b = *reinterpret_cast<const float4*>(&bgat[og * 4]);
    acc.x = fmaxf(acc.x + b.x, 0.f); acc.y = fmaxf(acc.y + b.y, 0.f);
    acc.z = fmaxf(acc.z + b.z, 0.f); acc.w = fmaxf(acc.w + b.w, 0.f);
    int g = bids[n];
    red_add_v4(&g_pooled[g * D_GAT + og * 4], acc);
    if (og == 0) atomicAdd(&g_cnt[g], 1.f);
}

// ---------------- K7: MLP head, one block per graph ----------------
__global__ void k_head(const float* __restrict__ Wfc1, const float* __restrict__ bfc1,
                       const float* __restrict__ Wfc2, const float* __restrict__ bfc2,
                       float* __restrict__ out) {
    int g = blockIdx.x;
    int h = threadIdx.x;
    __shared__ float sp[D_GAT];
    __shared__ float red[HID];
    if (h < D_GAT) {
        float c = fmaxf(g_cnt[g], 1.f);
        sp[h] = g_pooled[g * D_GAT + h] / c;
    }
    __syncthreads();
    float acc = __ldg(&bfc1[h]);
#pragma unroll 8
    for (int k = 0; k < D_GAT; k++) acc += sp[k] * __ldg(&Wfc1[k * HID + h]);
    acc = fmaxf(acc, 0.f);
    red[h] = acc * __ldg(&Wfc2[h]);
    __syncthreads();
    for (int s = HID / 2; s > 0; s >>= 1) {
        if (h < s) red[h] += red[h + s];
        __syncthreads();
    }
    if (h == 0) out[g] = red[0] + __ldg(&bfc2[0]);
}

// ---------------- launch ----------------
extern "C" void kernel_launch(void* const* d_in, const int* in_sizes, int n_in,
                              void* d_out, int out_size) {
    const float* x     = (const float*)d_in[0];
    const int*   ei    = (const int*)d_in[1];     // int32 (JAX x64 disabled)
    const float* ea    = (const float*)d_in[2];
    const int*   bids  = (const int*)d_in[3];     // int32
    const float* We    = (const float*)d_in[4];
    const float* be    = (const float*)d_in[5];
    const float* Wroot = (const float*)d_in[6];
    const float* bconv = (const float*)d_in[7];
    const float* Wgat  = (const float*)d_in[8];
    const float* a_src = (const float*)d_in[9];
    const float* a_dst = (const float*)d_in[10];
    const float* bgat  = (const float*)d_in[11];
    const float* Wfc1  = (const float*)d_in[12];
    const float* bfc1  = (const float*)d_in[13];
    const float* Wfc2  = (const float*)d_in[14];
    const float* bfc2  = (const float*)d_in[15];
    float* out = (float*)d_out;

    k_hist<<<256, 256>>>(ei, We);                          // idx 0
    k_scan<<<2, 1024>>>();                                 // idx 1
    k_scatter<<<(N_EDGES / 2 + 255) / 256, 256>>>(ei);     // idx 2
    k_nnconv<<<N_NODES / 16, 256>>>(x, ea);                // idx 3 (profiled)
    k_node1<<<N_NODES / 8, 128>>>(x, Wroot, be, bconv, Wgat, a_src, a_dst);
    k_softmax<<<N_NODES / 8, 256>>>();
    k_gatagg<<<N_NODES / 16, 256>>>(bids, bgat);
    k_head<<<N_GRAPHS, HID>>>(Wfc1, bfc1, Wfc2, bfc2, out);
}

// round 16
// speedup vs baseline: 2.7340x; 1.0980x over previous
#include <cuda_runtime.h>

#define N_NODES  20000
#define N_EDGES  320000
#define F_EDGE   32
#define D_IN     16
#define D_NN     16
#define D_GAT    64
#define HID      128
#define N_GRAPHS 64
#define NEG_SLOPE 0.2f

// ---------------- scratch (zero-initialized at load; hist self-cleaned by k_scan) ----------------
static __device__ __align__(16) float g_WeT[F_EDGE * D_IN * D_NN];   // WeT[f][o][i] == row p=f*16+o
static __device__ __align__(16) float g_agg[N_NODES * D_NN];
static __device__ __align__(16) float g_hp[N_NODES * D_GAT];
static __device__ __align__(16) float g_pooled[N_GRAPHS * D_GAT];
static __device__ float g_scs[N_NODES];
static __device__ float g_scd[N_NODES];
static __device__ float g_eself[N_NODES];
static __device__ float g_selfw[N_NODES];
static __device__ float g_invden[N_NODES];
static __device__ float g_cnt[N_GRAPHS];
// sorting scratch
static __device__ int g_hist_src[N_NODES], g_hist_dst[N_NODES];
static __device__ int g_rp_src[N_NODES + 1], g_rp_dst[N_NODES + 1];
static __device__ int g_rank_s[N_EDGES], g_rank_d[N_EDGES];   // per-edge rank within its node (from k_hist)
static __device__ __align__(8) int2 g_se_ed[N_EDGES];  // by-src order: (edge id, dst)
static __device__ int g_de_s[N_EDGES];                 // by-dst order: src ids
static __device__ float g_ev[N_EDGES];                 // softmax buffer

// ---------------- helpers ----------------
__device__ __forceinline__ void red_add_v4(float* p, float4 v) {
    asm volatile("red.global.add.v4.f32 [%0], {%1,%2,%3,%4};"
                 :: "l"(p), "f"(v.x), "f"(v.y), "f"(v.z), "f"(v.w) : "memory");
}
__device__ __forceinline__ void red_add_f32(float* p, float v) {
    asm volatile("red.global.add.f32 [%0], %1;" :: "l"(p), "f"(v) : "memory");
}
__device__ __forceinline__ float lrelu(float v) { return v > 0.f ? v : NEG_SLOPE * v; }

// ---------------- K0: histograms (recording per-edge ranks) + WeT transpose + zeroing ----------------
__global__ void k_hist(const int* __restrict__ ei, const float* __restrict__ We) {
    int t = blockIdx.x * blockDim.x + threadIdx.x;
    int stride = gridDim.x * blockDim.x;
    for (int i = t; i < F_EDGE * D_IN * D_NN; i += stride) {
        int f = i >> 8, r = i & 255, o = r >> 4, ii = r & 15;
        g_WeT[(f << 8) + (o << 4) + ii] = We[(f << 8) + (ii << 4) + o];
    }
    for (int i = t; i < N_NODES * D_NN; i += stride) g_agg[i] = 0.f;
    for (int i = t; i < N_GRAPHS * D_GAT; i += stride) g_pooled[i] = 0.f;
    for (int i = t; i < N_GRAPHS; i += stride) g_cnt[i] = 0.f;
    for (int e = t; e < N_EDGES; e += stride) {
        g_rank_s[e] = atomicAdd(&g_hist_src[ei[e]], 1);
        g_rank_d[e] = atomicAdd(&g_hist_dst[ei[N_EDGES + e]], 1);
    }
}

// ---------------- K1: exclusive scan of both histograms (shfl-based, self-cleans hist) ----------------
#define SCAN_CHUNK 20
__global__ void k_scan() {
    int* hist = (blockIdx.x == 0) ? g_hist_src : g_hist_dst;
    int* rp   = (blockIdx.x == 0) ? g_rp_src   : g_rp_dst;
    __shared__ int wsum[32];
    int tid = threadIdx.x;
    int lane = tid & 31, wid = tid >> 5;
    int base = tid * SCAN_CHUNK;
    int local[SCAN_CHUNK];
    int s = 0;
#pragma unroll
    for (int k = 0; k < SCAN_CHUNK; k++) {
        int idx = base + k;
        int v = 0;
        if (idx < N_NODES) { v = hist[idx]; hist[idx] = 0; }   // read + self-clean
        local[k] = s; s += v;
    }
    int sc = s;
#pragma unroll
    for (int off = 1; off < 32; off <<= 1) {
        int tv = __shfl_up_sync(0xffffffffu, sc, off);
        if (lane >= off) sc += tv;
    }
    if (lane == 31) wsum[wid] = sc;
    __syncthreads();
    if (wid == 0) {
        int v = wsum[lane];
#pragma unroll
        for (int off = 1; off < 32; off <<= 1) {
            int tv = __shfl_up_sync(0xffffffffu, v, off);
            if (lane >= off) v += tv;
        }
        wsum[lane] = v;
    }
    __syncthreads();
    int offset = sc - s + (wid > 0 ? wsum[wid - 1] : 0);   // exclusive prefix of this thread
#pragma unroll
    for (int k = 0; k < SCAN_CHUNK; k++) {
        int idx = base + k;
        if (idx < N_NODES) rp[idx] = offset + local[k];
    }
    if (tid == 1023) rp[N_NODES] = offset + s;
}

// ---------------- K2: scatter into both sorted orders — NO atomics (ranks from k_hist) ----------------
__global__ void k_scatter(const int* __restrict__ ei) {
    int t = blockIdx.x * blockDim.x + threadIdx.x;
    int e0 = 2 * t, e1 = 2 * t + 1;
    if (e0 >= N_EDGES) return;
    int s0 = ei[e0], d0 = ei[N_EDGES + e0];
    int p0 = g_rp_src[s0] + g_rank_s[e0];
    int q0 = g_rp_dst[d0] + g_rank_d[e0];
    g_se_ed[p0] = make_int2(e0, d0);
    g_de_s[q0] = s0;
    if (e1 < N_EDGES) {
        int s1 = ei[e1], d1 = ei[N_EDGES + e1];
        int p1 = g_rp_src[s1] + g_rank_s[e1];
        int q1 = g_rp_dst[d1] + g_rank_d[e1];
        g_se_ed[p1] = make_int2(e1, d1);
        g_de_s[q1] = s1;
    }
}

// ---------------- K3 (profiled slot): NNConv v9 — block-cooperative X2 build (16 nodes/block) ----------------
#define EA_CHUNK 8
__global__ void __launch_bounds__(256, 3) k_nnconv(const float* __restrict__ x,
                                                   const float* __restrict__ ea) {
    __shared__ __align__(16) float s_X2[16][512];               // 32 KB  [node][f*16+o]
    __shared__ __align__(16) float s_x[16][16];                 // 1 KB
    __shared__ __align__(16) float s_ea[8][EA_CHUNK][F_EDGE];   // 8 KB
    int tid = threadIdx.x;
    int nb0 = blockIdx.x * 16;

    // phase 0: stage x rows (fully coalesced)
    s_x[tid >> 4][tid & 15] = x[(nb0 + (tid >> 4)) * D_IN + (tid & 15)];
    __syncthreads();

    // phase 1: build X2 for all 16 nodes
    {
        int p0 = tid, p1 = tid + 256;
        const float4* wa = reinterpret_cast<const float4*>(&g_WeT[p0 << 4]);
        const float4* wb = reinterpret_cast<const float4*>(&g_WeT[p1 << 4]);
        float4 wa0 = wa[0], wa1 = wa[1], wa2 = wa[2], wa3 = wa[3];
        float4 wb0 = wb[0], wb1 = wb[1], wb2 = wb[2], wb3 = wb[3];
#pragma unroll
        for (int n = 0; n < 16; n++) {
            const float4* xv = reinterpret_cast<const float4*>(&s_x[n][0]);
            float4 x0 = xv[0], x1 = xv[1], x2 = xv[2], x3 = xv[3];
            float a0 = wa0.x * x0.x + wa0.y * x0.y + wa0.z * x0.z + wa0.w * x0.w;
            float a1 = wa1.x * x1.x + wa1.y * x1.y + wa1.z * x1.z + wa1.w * x1.w;
            float a2 = wa2.x * x2.x + wa2.y * x2.y + wa2.z * x2.z + wa2.w * x2.w;
            float a3 = wa3.x * x3.x + wa3.y * x3.y + wa3.z * x3.z + wa3.w * x3.w;
            float b0 = wb0.x * x0.x + wb0.y * x0.y + wb0.z * x0.z + wb0.w * x0.w;
            float b1 = wb1.x * x1.x + wb1.y * x1.y + wb1.z * x1.z + wb1.w * x1.w;
            float b2 = wb2.x * x2.x + wb2.y * x2.y + wb2.z * x2.z + wb2.w * x2.w;
            float b3 = wb3.x * x3.x + wb3.y * x3.y + wb3.z * x3.z + wb3.w * x3.w;
            s_X2[n][p0] = (a0 + a1) + (a2 + a3);
            s_X2[n][p1] = (b0 + b1) + (b2 + b3);
        }
    }
    __syncthreads();

    // phase 2: per-warp edge loops (warp wl -> local nodes 2wl, 2wl+1)
    int wl = tid >> 5;
    int lane = tid & 31;
    int g = lane >> 4, o = lane & 15;
    int n0l = 2 * wl, n1l = 2 * wl + 1;

    float X2a[16], X2b[16];
#pragma unroll
    for (int k = 0; k < 16; k++) {
        X2a[k] = s_X2[n0l][((16 * g + k) << 4) + o];
        X2b[k] = s_X2[n1l][((16 * g + k) << 4) + o];
    }

#pragma unroll
    for (int half = 0; half < 2; half++) {
        int n = nb0 + (half ? n1l : n0l);
        int beg = g_rp_src[n], end = g_rp_src[n + 1];
        for (int base = beg; base < end; base += EA_CHUNK) {
            int nleft = min(EA_CHUNK, end - base);
            // stage ea rows for up to 8 edges (2 coalesced rounds)
#pragma unroll
            for (int r = 0; r < 2; r++) {
                int item = lane + 32 * r;         // 0..63
                int i = item >> 3, c = item & 7;
                if (i < nleft) {
                    int e = g_se_ed[base + i].x;
                    *reinterpret_cast<float4*>(&s_ea[wl][i][c * 4]) =
                        *reinterpret_cast<const float4*>(&ea[(size_t)e * F_EDGE + c * 4]);
                }
            }
            __syncwarp();
#pragma unroll 2
            for (int i = 0; i < nleft; i++) {
                int d = g_se_ed[base + i].y;   // broadcast, L1-hot
                const float4* ar = reinterpret_cast<const float4*>(&s_ea[wl][i][g * 16]);
                float4 a0 = ar[0], a1 = ar[1], a2 = ar[2], a3 = ar[3];
                float q0, q1, q2, q3;
                if (half == 0) {
                    q0 = a0.x * X2a[0]  + a0.y * X2a[1]  + a0.z * X2a[2]  + a0.w * X2a[3];
                    q1 = a1.x * X2a[4]  + a1.y * X2a[5]  + a1.z * X2a[6]  + a1.w * X2a[7];
                    q2 = a2.x * X2a[8]  + a2.y * X2a[9]  + a2.z * X2a[10] + a2.w * X2a[11];
                    q3 = a3.x * X2a[12] + a3.y * X2a[13] + a3.z * X2a[14] + a3.w * X2a[15];
                } else {
                    q0 = a0.x * X2b[0]  + a0.y * X2b[1]  + a0.z * X2b[2]  + a0.w * X2b[3];
                    q1 = a1.x * X2b[4]  + a1.y * X2b[5]  + a1.z * X2b[6]  + a1.w * X2b[7];
                    q2 = a2.x * X2b[8]  + a2.y * X2b[9]  + a2.z * X2b[10] + a2.w * X2b[11];
                    q3 = a3.x * X2b[12] + a3.y * X2b[13] + a3.z * X2b[14] + a3.w * X2b[15];
                }
                float p = (q0 + q1) + (q2 + q3);
                p += __shfl_xor_sync(0xffffffffu, p, 16);
                if (lane < 16) red_add_f32(&g_agg[d * D_NN + lane], p);
            }
            __syncwarp();
        }
    }
}

// ---------------- K4: cooperative node transform (16 threads/node; broadcast x loads, no shfl chain) ----------------
__global__ void k_node1(const float* __restrict__ x, const float* __restrict__ Wroot,
                        const float* __restrict__ be, const float* __restrict__ bconv,
                        const float* __restrict__ Wgat,
                        const float* __restrict__ a_src, const float* __restrict__ a_dst) {
    int tid = threadIdx.x;
    int n = blockIdx.x * 8 + (tid >> 4);   // exact grid
    int j = tid & 15;
    __shared__ float sh[128];

    // each of the node's 16 threads loads the full x row (same L1 line -> broadcast)
    float4 x0 = *reinterpret_cast<const float4*>(&x[n * D_IN + 0]);
    float4 x1 = *reinterpret_cast<const float4*>(&x[n * D_IN + 4]);
    float4 x2 = *reinterpret_cast<const float4*>(&x[n * D_IN + 8]);
    float4 x3 = *reinterpret_cast<const float4*>(&x[n * D_IN + 12]);
    float xr[D_IN] = {x0.x, x0.y, x0.z, x0.w, x1.x, x1.y, x1.z, x1.w,
                      x2.x, x2.y, x2.z, x2.w, x3.x, x3.y, x3.z, x3.w};

    float a = g_agg[n * D_NN + j] + __ldg(&bconv[j]);
#pragma unroll
    for (int i = 0; i < D_IN; i++)
        a += xr[i] * (__ldg(&Wroot[i * D_NN + j]) + __ldg(&be[i * D_NN + j]));
    float hj = fmaxf(a, 0.f);
    sh[tid] = hj;
    __syncwarp();
    const float* shh = &sh[tid & ~15];

    float4 hp4 = make_float4(0.f, 0.f, 0.f, 0.f);
#pragma unroll
    for (int i = 0; i < D_NN; i++) {
        float hv = shh[i];
        float4 wg = *reinterpret_cast<const float4*>(&Wgat[i * D_GAT + j * 4]);
        hp4.x += hv * wg.x; hp4.y += hv * wg.y; hp4.z += hv * wg.z; hp4.w += hv * wg.w;
    }
    *reinterpret_cast<float4*>(&g_hp[(size_t)n * D_GAT + j * 4]) = hp4;

    float4 as = *reinterpret_cast<const float4*>(&a_src[j * 4]);
    float4 ad = *reinterpret_cast<const float4*>(&a_dst[j * 4]);
    float ss = hp4.x * as.x + hp4.y * as.y + hp4.z * as.z + hp4.w * as.w;
    float sd = hp4.x * ad.x + hp4.y * ad.y + hp4.z * ad.z + hp4.w * ad.w;
#pragma unroll
    for (int off = 8; off >= 1; off >>= 1) {
        ss += __shfl_xor_sync(0xffffffffu, ss, off, 16);
        sd += __shfl_xor_sync(0xffffffffu, sd, off, 16);
    }
    if (j == 0) {
        g_scs[n] = ss;
        g_scd[n] = sd;
        g_eself[n] = lrelu(ss + sd);
    }
}

// ---------------- K5: GAT softmax per dst node (warp/node, no atomics) ----------------
__global__ void k_softmax() {
    int n = blockIdx.x * 8 + (threadIdx.x >> 5);   // exact grid
    int lane = threadIdx.x & 31;
    int beg = g_rp_dst[n], end = g_rp_dst[n + 1];
    float scd_n = g_scd[n];
    float eself = g_eself[n];

    float m = eself;
    for (int j = beg + lane; j < end; j += 32) {
        float ev = lrelu(g_scs[g_de_s[j]] + scd_n);
        g_ev[j] = ev;
        m = fmaxf(m, ev);
    }
#pragma unroll
    for (int off = 16; off >= 1; off >>= 1)
        m = fmaxf(m, __shfl_xor_sync(0xffffffffu, m, off));

    float sum = 0.f;
    for (int j = beg + lane; j < end; j += 32) {
        float ex = __expf(g_ev[j] - m);
        g_ev[j] = ex;
        sum += ex;
    }
    float exs = __expf(eself - m);
    if (lane == 0) sum += exs;
#pragma unroll
    for (int off = 16; off >= 1; off >>= 1)
        sum += __shfl_xor_sync(0xffffffffu, sum, off);
    if (lane == 0) {
        g_selfw[n] = exs;
        g_invden[n] = 1.f / sum;
    }
}

// ---------------- K6: GAT aggregate + bias/relu + mean-pool scatter (16 threads/node) ----------------
__global__ void k_gatagg(const int* __restrict__ bids, const float* __restrict__ bgat) {
    int tid = threadIdx.x;
    int n = blockIdx.x * 16 + (tid >> 4);   // exact grid
    int og = tid & 15;
    float inv = g_invden[n];
    float w0 = g_selfw[n] * inv;
    float4 acc = *reinterpret_cast<const float4*>(&g_hp[(size_t)n * D_GAT + og * 4]);
    acc.x *= w0; acc.y *= w0; acc.z *= w0; acc.w *= w0;
    int beg = g_rp_dst[n], end = g_rp_dst[n + 1];
    for (int j = beg; j < end; j++) {
        int s = g_de_s[j];
        float w = g_ev[j] * inv;
        float4 v = *reinterpret_cast<const float4*>(&g_hp[(size_t)s * D_GAT + og * 4]);
        acc.x += w * v.x; acc.y += w * v.y; acc.z += w * v.z; acc.w += w * v.w;
    }
    float4 b = *reinterpret_cast<const float4*>(&bgat[og * 4]);
    acc.x = fmaxf(acc.x + b.x, 0.f); acc.y = fmaxf(acc.y + b.y, 0.f);
    acc.z = fmaxf(acc.z + b.z, 0.f); acc.w = fmaxf(acc.w + b.w, 0.f);
    int g = bids[n];
    red_add_v4(&g_pooled[g * D_GAT + og * 4], acc);
    if (og == 0) atomicAdd(&g_cnt[g], 1.f);
}

// ---------------- K7: MLP head, one block per graph ----------------
__global__ void k_head(const float* __restrict__ Wfc1, const float* __restrict__ bfc1,
                       const float* __restrict__ Wfc2, const float* __restrict__ bfc2,
                       float* __restrict__ out) {
    int g = blockIdx.x;
    int h = threadIdx.x;
    __shared__ float sp[D_GAT];
    __shared__ float red[HID];
    if (h < D_GAT) {
        float c = fmaxf(g_cnt[g], 1.f);
        sp[h] = g_pooled[g * D_GAT + h] / c;
    }
    __syncthreads();
    float acc = __ldg(&bfc1[h]);
#pragma unroll 8
    for (int k = 0; k < D_GAT; k++) acc += sp[k] * __ldg(&Wfc1[k * HID + h]);
    acc = fmaxf(acc, 0.f);
    red[h] = acc * __ldg(&Wfc2[h]);
    __syncthreads();
    for (int s = HID / 2; s > 0; s >>= 1) {
        if (h < s) red[h] += red[h + s];
        __syncthreads();
    }
    if (h == 0) out[g] = red[0] + __ldg(&bfc2[0]);
}

// ---------------- launch ----------------
extern "C" void kernel_launch(void* const* d_in, const int* in_sizes, int n_in,
                              void* d_out, int out_size) {
    const float* x     = (const float*)d_in[0];
    const int*   ei    = (const int*)d_in[1];     // int32 (JAX x64 disabled)
    const float* ea    = (const float*)d_in[2];
    const int*   bids  = (const int*)d_in[3];     // int32
    const float* We    = (const float*)d_in[4];
    const float* be    = (const float*)d_in[5];
    const float* Wroot = (const float*)d_in[6];
    const float* bconv = (const float*)d_in[7];
    const float* Wgat  = (const float*)d_in[8];
    const float* a_src = (const float*)d_in[9];
    const float* a_dst = (const float*)d_in[10];
    const float* bgat  = (const float*)d_in[11];
    const float* Wfc1  = (const float*)d_in[12];
    const float* bfc1  = (const float*)d_in[13];
    const float* Wfc2  = (const float*)d_in[14];
    const float* bfc2  = (const float*)d_in[15];
    float* out = (float*)d_out;

    k_hist<<<256, 256>>>(ei, We);                          // idx 0
    k_scan<<<2, 1024>>>();                                 // idx 1
    k_scatter<<<(N_EDGES / 2 + 255) / 256, 256>>>(ei);     // idx 2
    k_nnconv<<<N_NODES / 16, 256>>>(x, ea);                // idx 3 (profiled)
    k_node1<<<N_NODES / 8, 128>>>(x, Wroot, be, bconv, Wgat, a_src, a_dst);
    k_softmax<<<N_NODES / 8, 256>>>();
    k_gatagg<<<N_NODES / 16, 256>>>(bids, bgat);
    k_head<<<N_GRAPHS, HID>>>(Wfc1, bfc1, Wfc2, bfc2, out);
}

// round 17
// speedup vs baseline: 2.7903x; 1.0206x over previous
#include <cuda_runtime.h>

#define N_NODES  20000
#define N_EDGES  320000
#define F_EDGE   32
#define D_IN     16
#define D_NN     16
#define D_GAT    64
#define HID      128
#define N_GRAPHS 64
#define NEG_SLOPE 0.2f

// ---------------- scratch (zero-initialized at load; hist self-cleaned by k_scan) ----------------
static __device__ __align__(16) float g_WeT[F_EDGE * D_IN * D_NN];   // WeT[f][o][i] == row p=f*16+o
static __device__ __align__(16) float g_agg[N_NODES * D_NN];
static __device__ __align__(16) float g_hp[N_NODES * D_GAT];
static __device__ __align__(16) float g_pooled[N_GRAPHS * D_GAT];
static __device__ float g_scs[N_NODES];
static __device__ float g_scd[N_NODES];
static __device__ float g_eself[N_NODES];
static __device__ float g_selfw[N_NODES];
static __device__ float g_invden[N_NODES];
static __device__ float g_cnt[N_GRAPHS];
// sorting scratch
static __device__ int g_hist_src[N_NODES], g_hist_dst[N_NODES];
static __device__ int g_rp_src[N_NODES + 1], g_rp_dst[N_NODES + 1];
static __device__ int g_rank_s[N_EDGES], g_rank_d[N_EDGES];   // per-edge rank within its node (from k_hist)
static __device__ __align__(8) int2 g_se_ed[N_EDGES];  // by-src order: (edge id, dst)
static __device__ int g_de_s[N_EDGES];                 // by-dst order: src ids
static __device__ float g_ev[N_EDGES];                 // softmax buffer

// ---------------- helpers ----------------
__device__ __forceinline__ void red_add_v4(float* p, float4 v) {
    asm volatile("red.global.add.v4.f32 [%0], {%1,%2,%3,%4};"
                 :: "l"(p), "f"(v.x), "f"(v.y), "f"(v.z), "f"(v.w) : "memory");
}
__device__ __forceinline__ void red_add_f32(float* p, float v) {
    asm volatile("red.global.add.f32 [%0], %1;" :: "l"(p), "f"(v) : "memory");
}
__device__ __forceinline__ float lrelu(float v) { return v > 0.f ? v : NEG_SLOPE * v; }

// ---------------- K0: histograms (recording per-edge ranks) + WeT transpose + zeroing ----------------
__global__ void k_hist(const int* __restrict__ ei, const float* __restrict__ We) {
    int t = blockIdx.x * blockDim.x + threadIdx.x;
    int stride = gridDim.x * blockDim.x;
    for (int i = t; i < F_EDGE * D_IN * D_NN; i += stride) {
        int f = i >> 8, r = i & 255, o = r >> 4, ii = r & 15;
        g_WeT[(f << 8) + (o << 4) + ii] = We[(f << 8) + (ii << 4) + o];
    }
    for (int i = t; i < N_NODES * D_NN; i += stride) g_agg[i] = 0.f;
    for (int i = t; i < N_GRAPHS * D_GAT; i += stride) g_pooled[i] = 0.f;
    for (int i = t; i < N_GRAPHS; i += stride) g_cnt[i] = 0.f;
    for (int e = t; e < N_EDGES; e += stride) {
        g_rank_s[e] = atomicAdd(&g_hist_src[ei[e]], 1);
        g_rank_d[e] = atomicAdd(&g_hist_dst[ei[N_EDGES + e]], 1);
    }
}

// ---------------- K1: exclusive scan of both histograms (shfl-based, self-cleans hist) ----------------
#define SCAN_CHUNK 20
__global__ void k_scan() {
    int* hist = (blockIdx.x == 0) ? g_hist_src : g_hist_dst;
    int* rp   = (blockIdx.x == 0) ? g_rp_src   : g_rp_dst;
    __shared__ int wsum[32];
    int tid = threadIdx.x;
    int lane = tid & 31, wid = tid >> 5;
    int base = tid * SCAN_CHUNK;
    int local[SCAN_CHUNK];
    int s = 0;
#pragma unroll
    for (int k = 0; k < SCAN_CHUNK; k++) {
        int idx = base + k;
        int v = 0;
        if (idx < N_NODES) { v = hist[idx]; hist[idx] = 0; }   // read + self-clean
        local[k] = s; s += v;
    }
    int sc = s;
#pragma unroll
    for (int off = 1; off < 32; off <<= 1) {
        int tv = __shfl_up_sync(0xffffffffu, sc, off);
        if (lane >= off) sc += tv;
    }
    if (lane == 31) wsum[wid] = sc;
    __syncthreads();
    if (wid == 0) {
        int v = wsum[lane];
#pragma unroll
        for (int off = 1; off < 32; off <<= 1) {
            int tv = __shfl_up_sync(0xffffffffu, v, off);
            if (lane >= off) v += tv;
        }
        wsum[lane] = v;
    }
    __syncthreads();
    int offset = sc - s + (wid > 0 ? wsum[wid - 1] : 0);   // exclusive prefix of this thread
#pragma unroll
    for (int k = 0; k < SCAN_CHUNK; k++) {
        int idx = base + k;
        if (idx < N_NODES) rp[idx] = offset + local[k];
    }
    if (tid == 1023) rp[N_NODES] = offset + s;
}

// ---------------- K2: scatter into both sorted orders — NO atomics (ranks from k_hist) ----------------
__global__ void k_scatter(const int* __restrict__ ei) {
    int t = blockIdx.x * blockDim.x + threadIdx.x;
    int e0 = 2 * t, e1 = 2 * t + 1;
    if (e0 >= N_EDGES) return;
    int s0 = ei[e0], d0 = ei[N_EDGES + e0];
    int p0 = g_rp_src[s0] + g_rank_s[e0];
    int q0 = g_rp_dst[d0] + g_rank_d[e0];
    g_se_ed[p0] = make_int2(e0, d0);
    g_de_s[q0] = s0;
    if (e1 < N_EDGES) {
        int s1 = ei[e1], d1 = ei[N_EDGES + e1];
        int p1 = g_rp_src[s1] + g_rank_s[e1];
        int q1 = g_rp_dst[d1] + g_rank_d[e1];
        g_se_ed[p1] = make_int2(e1, d1);
        g_de_s[q1] = s1;
    }
}

// ---------------- K3 (profiled slot): NNConv v10 — block X2 build; sequential halves, 4 blocks/SM ----------------
#define EA_CHUNK 8
__global__ void __launch_bounds__(256, 4) k_nnconv(const float* __restrict__ x,
                                                   const float* __restrict__ ea) {
    __shared__ __align__(16) float s_X2[16][512];               // 32 KB  [node][f*16+o]
    __shared__ __align__(16) float s_x[16][16];                 // 1 KB
    __shared__ __align__(16) float s_ea[8][EA_CHUNK][F_EDGE];   // 8 KB
    int tid = threadIdx.x;
    int nb0 = blockIdx.x * 16;

    // phase 0: stage x rows (fully coalesced)
    s_x[tid >> 4][tid & 15] = x[(nb0 + (tid >> 4)) * D_IN + (tid & 15)];
    __syncthreads();

    // phase 1: build X2 for all 16 nodes (WeT read ONCE per block)
    {
        int p0 = tid, p1 = tid + 256;
        const float4* wa = reinterpret_cast<const float4*>(&g_WeT[p0 << 4]);
        const float4* wb = reinterpret_cast<const float4*>(&g_WeT[p1 << 4]);
        float4 wa0 = wa[0], wa1 = wa[1], wa2 = wa[2], wa3 = wa[3];
        float4 wb0 = wb[0], wb1 = wb[1], wb2 = wb[2], wb3 = wb[3];
#pragma unroll
        for (int n = 0; n < 16; n++) {
            const float4* xv = reinterpret_cast<const float4*>(&s_x[n][0]);
            float4 x0 = xv[0], x1 = xv[1], x2 = xv[2], x3 = xv[3];
            float a0 = wa0.x * x0.x + wa0.y * x0.y + wa0.z * x0.z + wa0.w * x0.w;
            float a1 = wa1.x * x1.x + wa1.y * x1.y + wa1.z * x1.z + wa1.w * x1.w;
            float a2 = wa2.x * x2.x + wa2.y * x2.y + wa2.z * x2.z + wa2.w * x2.w;
            float a3 = wa3.x * x3.x + wa3.y * x3.y + wa3.z * x3.z + wa3.w * x3.w;
            float b0 = wb0.x * x0.x + wb0.y * x0.y + wb0.z * x0.z + wb0.w * x0.w;
            float b1 = wb1.x * x1.x + wb1.y * x1.y + wb1.z * x1.z + wb1.w * x1.w;
            float b2 = wb2.x * x2.x + wb2.y * x2.y + wb2.z * x2.z + wb2.w * x2.w;
            float b3 = wb3.x * x3.x + wb3.y * x3.y + wb3.z * x3.z + wb3.w * x3.w;
            s_X2[n][p0] = (a0 + a1) + (a2 + a3);
            s_X2[n][p1] = (b0 + b1) + (b2 + b3);
        }
    }
    __syncthreads();

    // phase 2: per-warp edge loops, halves processed SEQUENTIALLY (one 16-reg X2 live)
    int wl = tid >> 5;
    int lane = tid & 31;
    int g = lane >> 4, o = lane & 15;

#pragma unroll 1
    for (int half = 0; half < 2; half++) {
        int nl = 2 * wl + half;
        float X2[16];
#pragma unroll
        for (int k = 0; k < 16; k++)
            X2[k] = s_X2[nl][((16 * g + k) << 4) + o];

        int n = nb0 + nl;
        int beg = g_rp_src[n], end = g_rp_src[n + 1];
        for (int base = beg; base < end; base += EA_CHUNK) {
            int nleft = min(EA_CHUNK, end - base);
            // stage ea rows for up to 8 edges (2 coalesced rounds)
#pragma unroll
            for (int r = 0; r < 2; r++) {
                int item = lane + 32 * r;         // 0..63
                int i = item >> 3, c = item & 7;
                if (i < nleft) {
                    int e = g_se_ed[base + i].x;
                    *reinterpret_cast<float4*>(&s_ea[wl][i][c * 4]) =
                        *reinterpret_cast<const float4*>(&ea[(size_t)e * F_EDGE + c * 4]);
                }
            }
            __syncwarp();
#pragma unroll 2
            for (int i = 0; i < nleft; i++) {
                int d = g_se_ed[base + i].y;   // broadcast, L1-hot
                const float4* ar = reinterpret_cast<const float4*>(&s_ea[wl][i][g * 16]);
                float4 a0 = ar[0], a1 = ar[1], a2 = ar[2], a3 = ar[3];
                float q0 = a0.x * X2[0]  + a0.y * X2[1]  + a0.z * X2[2]  + a0.w * X2[3];
                float q1 = a1.x * X2[4]  + a1.y * X2[5]  + a1.z * X2[6]  + a1.w * X2[7];
                float q2 = a2.x * X2[8]  + a2.y * X2[9]  + a2.z * X2[10] + a2.w * X2[11];
                float q3 = a3.x * X2[12] + a3.y * X2[13] + a3.z * X2[14] + a3.w * X2[15];
                float p = (q0 + q1) + (q2 + q3);
                p += __shfl_xor_sync(0xffffffffu, p, 16);
                if (lane < 16) red_add_f32(&g_agg[d * D_NN + lane], p);
            }
            __syncwarp();
        }
    }
}

// ---------------- K4: cooperative node transform (16 threads/node; broadcast x loads) ----------------
__global__ void k_node1(const float* __restrict__ x, const float* __restrict__ Wroot,
                        const float* __restrict__ be, const float* __restrict__ bconv,
                        const float* __restrict__ Wgat,
                        const float* __restrict__ a_src, const float* __restrict__ a_dst) {
    int tid = threadIdx.x;
    int n = blockIdx.x * 8 + (tid >> 4);   // exact grid
    int j = tid & 15;
    __shared__ float sh[128];

    float4 x0 = *reinterpret_cast<const float4*>(&x[n * D_IN + 0]);
    float4 x1 = *reinterpret_cast<const float4*>(&x[n * D_IN + 4]);
    float4 x2 = *reinterpret_cast<const float4*>(&x[n * D_IN + 8]);
    float4 x3 = *reinterpret_cast<const float4*>(&x[n * D_IN + 12]);
    float xr[D_IN] = {x0.x, x0.y, x0.z, x0.w, x1.x, x1.y, x1.z, x1.w,
                      x2.x, x2.y, x2.z, x2.w, x3.x, x3.y, x3.z, x3.w};

    float a = g_agg[n * D_NN + j] + __ldg(&bconv[j]);
#pragma unroll
    for (int i = 0; i < D_IN; i++)
        a += xr[i] * (__ldg(&Wroot[i * D_NN + j]) + __ldg(&be[i * D_NN + j]));
    float hj = fmaxf(a, 0.f);
    sh[tid] = hj;
    __syncwarp();
    const float* shh = &sh[tid & ~15];

    float4 hp4 = make_float4(0.f, 0.f, 0.f, 0.f);
#pragma unroll
    for (int i = 0; i < D_NN; i++) {
        float hv = shh[i];
        float4 wg = *reinterpret_cast<const float4*>(&Wgat[i * D_GAT + j * 4]);
        hp4.x += hv * wg.x; hp4.y += hv * wg.y; hp4.z += hv * wg.z; hp4.w += hv * wg.w;
    }
    *reinterpret_cast<float4*>(&g_hp[(size_t)n * D_GAT + j * 4]) = hp4;

    float4 as = *reinterpret_cast<const float4*>(&a_src[j * 4]);
    float4 ad = *reinterpret_cast<const float4*>(&a_dst[j * 4]);
    float ss = hp4.x * as.x + hp4.y * as.y + hp4.z * as.z + hp4.w * as.w;
    float sd = hp4.x * ad.x + hp4.y * ad.y + hp4.z * ad.z + hp4.w * ad.w;
#pragma unroll
    for (int off = 8; off >= 1; off >>= 1) {
        ss += __shfl_xor_sync(0xffffffffu, ss, off, 16);
        sd += __shfl_xor_sync(0xffffffffu, sd, off, 16);
    }
    if (j == 0) {
        g_scs[n] = ss;
        g_scd[n] = sd;
        g_eself[n] = lrelu(ss + sd);
    }
}

// ---------------- K5: GAT softmax per dst node (warp/node, no atomics) ----------------
__global__ void k_softmax() {
    int n = blockIdx.x * 8 + (threadIdx.x >> 5);   // exact grid
    int lane = threadIdx.x & 31;
    int beg = g_rp_dst[n], end = g_rp_dst[n + 1];
    float scd_n = g_scd[n];
    float eself = g_eself[n];

    float m = eself;
    for (int j = beg + lane; j < end; j += 32) {
        float ev = lrelu(g_scs[g_de_s[j]] + scd_n);
        g_ev[j] = ev;
        m = fmaxf(m, ev);
    }
#pragma unroll
    for (int off = 16; off >= 1; off >>= 1)
        m = fmaxf(m, __shfl_xor_sync(0xffffffffu, m, off));

    float sum = 0.f;
    for (int j = beg + lane; j < end; j += 32) {
        float ex = __expf(g_ev[j] - m);
        g_ev[j] = ex;
        sum += ex;
    }
    float exs = __expf(eself - m);
    if (lane == 0) sum += exs;
#pragma unroll
    for (int off = 16; off >= 1; off >>= 1)
        sum += __shfl_xor_sync(0xffffffffu, sum, off);
    if (lane == 0) {
        g_selfw[n] = exs;
        g_invden[n] = 1.f / sum;
    }
}

// ---------------- K6: GAT aggregate + bias/relu + mean-pool scatter (16 threads/node) ----------------
__global__ void k_gatagg(const int* __restrict__ bids, const float* __restrict__ bgat) {
    int tid = threadIdx.x;
    int n = blockIdx.x * 16 + (tid >> 4);   // exact grid
    int og = tid & 15;
    float inv = g_invden[n];
    float w0 = g_selfw[n] * inv;
    float4 acc = *reinterpret_cast<const float4*>(&g_hp[(size_t)n * D_GAT + og * 4]);
    acc.x *= w0; acc.y *= w0; acc.z *= w0; acc.w *= w0;
    int beg = g_rp_dst[n], end = g_rp_dst[n + 1];
    for (int j = beg; j < end; j++) {
        int s = g_de_s[j];
        float w = g_ev[j] * inv;
        float4 v = *reinterpret_cast<const float4*>(&g_hp[(size_t)s * D_GAT + og * 4]);
        acc.x += w * v.x; acc.y += w * v.y; acc.z += w * v.z; acc.w += w * v.w;
    }
    float4 b = *reinterpret_cast<const float4*>(&bgat[og * 4]);
    acc.x = fmaxf(acc.x + b.x, 0.f); acc.y = fmaxf(acc.y + b.y, 0.f);
    acc.z = fmaxf(acc.z + b.z, 0.f); acc.w = fmaxf(acc.w + b.w, 0.f);
    int g = bids[n];
    red_add_v4(&g_pooled[g * D_GAT + og * 4], acc);
    if (og == 0) atomicAdd(&g_cnt[g], 1.f);
}

// ---------------- K7: MLP head, one block per graph ----------------
__global__ void k_head(const float* __restrict__ Wfc1, const float* __restrict__ bfc1,
                       const float* __restrict__ Wfc2, const float* __restrict__ bfc2,
                       float* __restrict__ out) {
    int g = blockIdx.x;
    int h = threadIdx.x;
    __shared__ float sp[D_GAT];
    __shared__ float red[HID];
    if (h < D_GAT) {
        float c = fmaxf(g_cnt[g], 1.f);
        sp[h] = g_pooled[g * D_GAT + h] / c;
    }
    __syncthreads();
    float acc = __ldg(&bfc1[h]);
#pragma unroll 8
    for (int k = 0; k < D_GAT; k++) acc += sp[k] * __ldg(&Wfc1[k * HID + h]);
    acc = fmaxf(acc, 0.f);
    red[h] = acc * __ldg(&Wfc2[h]);
    __syncthreads();
    for (int s = HID / 2; s > 0; s >>= 1) {
        if (h < s) red[h] += red[h + s];
        __syncthreads();
    }
    if (h == 0) out[g] = red[0] + __ldg(&bfc2[0]);
}

// ---------------- launch ----------------
extern "C" void kernel_launch(void* const* d_in, const int* in_sizes, int n_in,
                              void* d_out, int out_size) {
    const float* x     = (const float*)d_in[0];
    const int*   ei    = (const int*)d_in[1];     // int32 (JAX x64 disabled)
    const float* ea    = (const float*)d_in[2];
    const int*   bids  = (const int*)d_in[3];     // int32
    const float* We    = (const float*)d_in[4];
    const float* be    = (const float*)d_in[5];
    const float* Wroot = (const float*)d_in[6];
    const float* bconv = (const float*)d_in[7];
    const float* Wgat  = (const float*)d_in[8];
    const float* a_src = (const float*)d_in[9];
    const float* a_dst = (const float*)d_in[10];
    const float* bgat  = (const float*)d_in[11];
    const float* Wfc1  = (const float*)d_in[12];
    const float* bfc1  = (const float*)d_in[13];
    const float* Wfc2  = (const float*)d_in[14];
    const float* bfc2  = (const float*)d_in[15];
    float* out = (float*)d_out;

    k_hist<<<256, 256>>>(ei, We);                          // idx 0
    k_scan<<<2, 1024>>>();                                 // idx 1
    k_scatter<<<(N_EDGES / 2 + 255) / 256, 256>>>(ei);     // idx 2
    k_nnconv<<<N_NODES / 16, 256>>>(x, ea);                // idx 3 (profiled)
    k_node1<<<N_NODES / 8, 128>>>(x, Wroot, be, bconv, Wgat, a_src, a_dst);
    k_softmax<<<N_NODES / 8, 256>>>();
    k_gatagg<<<N_NODES / 16, 256>>>(bids, bgat);
    k_head<<<N_GRAPHS, HID>>>(Wfc1, bfc1, Wfc2, bfc2, out);
}